// round 11
// baseline (speedup 1.0000x reference)
#include <cuda_runtime.h>
#include <cuda_bf16.h>
#include <cstdint>

#define EPSF 1e-6f

constexpr int B_ = 8;
constexpr int S_ = 2048;
constexpr int T_ = 2048;
constexpr int E_ = 512;

constexpr int NSE = B_ * S_ * E_;               // 8388608
constexpr size_t NST = (size_t)B_ * S_ * T_;    // 33554432

// ---------------- scratch (device globals) ----------------
__device__ __nv_bfloat16 g_encH[NSE], g_encL[NSE];
__device__ __nv_bfloat16 g_emoH[NSE], g_emoL[NSE];
__device__ __nv_bfloat16 g_WqH[E_*E_], g_WqL[E_*E_];
__device__ __nv_bfloat16 g_WkH[E_*E_], g_WkL[E_*E_];
__device__ __nv_bfloat16 g_WvH[E_*E_], g_WvL[E_*E_];
__device__ __nv_bfloat16 g_WoH[E_*E_], g_WoL[E_*E_];
__device__ __nv_bfloat16 g_qH[NSE], g_qL[NSE];
__device__ __nv_bfloat16 g_kH[NSE], g_kL[NSE];
__device__ float         g_v[NSE];
__device__ __nv_bfloat16 g_vTH[NSE], g_vTL[NSE];
__device__ float         g_logits[NST];
__device__ __nv_bfloat16 g_pH[NST], g_pL[NST];
__device__ __nv_bfloat16 g_ctxH[NSE], g_ctxL[NSE];
__device__ float         g_tmp[NSE];

// ---------------- helpers ----------------
__device__ __forceinline__ uint32_t smem_u32(const void* p) {
    uint32_t a;
    asm("{ .reg .u64 t; cvta.to.shared.u64 t, %1; cvt.u32.u64 %0, t; }" : "=r"(a) : "l"(p));
    return a;
}
#define CP16(dst, src) asm volatile("cp.async.cg.shared.global [%0], [%1], 16;" :: "r"(dst), "l"(src))
#define CP_COMMIT()    asm volatile("cp.async.commit_group;")
#define CP_WAIT1()     asm volatile("cp.async.wait_group 1;")

__device__ __forceinline__ void ldsm4(uint32_t& r0, uint32_t& r1, uint32_t& r2, uint32_t& r3, uint32_t a) {
    asm volatile("ldmatrix.sync.aligned.m8n8.x4.shared.b16 {%0,%1,%2,%3}, [%4];"
                 : "=r"(r0), "=r"(r1), "=r"(r2), "=r"(r3) : "r"(a));
}
__device__ __forceinline__ void mma16816(float* c, const uint32_t* a, const uint32_t* b) {
    asm volatile("mma.sync.aligned.m16n8k16.row.col.f32.bf16.bf16.f32 "
                 "{%0,%1,%2,%3}, {%4,%5,%6,%7}, {%8,%9}, {%0,%1,%2,%3};"
                 : "+f"(c[0]), "+f"(c[1]), "+f"(c[2]), "+f"(c[3])
                 : "r"(a[0]), "r"(a[1]), "r"(a[2]), "r"(a[3]), "r"(b[0]), "r"(b[1]));
}
__device__ __forceinline__ uint32_t pack_hi2(float x, float y) {
    unsigned short hx = __bfloat16_as_ushort(__float2bfloat16(x));
    unsigned short hy = __bfloat16_as_ushort(__float2bfloat16(y));
    return (uint32_t)hx | ((uint32_t)hy << 16);
}
__device__ __forceinline__ uint32_t pack_lo2(float x, float y) {
    float hx = __bfloat162float(__float2bfloat16(x));
    float hy = __bfloat162float(__float2bfloat16(y));
    unsigned short lx = __bfloat16_as_ushort(__float2bfloat16(x - hx));
    unsigned short ly = __bfloat16_as_ushort(__float2bfloat16(y - hy));
    return (uint32_t)lx | ((uint32_t)ly << 16);
}

// ---------------------------------------------------------------------------
// bf16-split GEMM via mma.sync, NT form: C[m,n] = sum_k A[m,k]*B[n,k].
// Block tile 128x256, BK=32, 256 threads (8 warps, warp tile 64x64),
// 3-stage cp.async. B fragments resident (32 regs), A streamed per-mi:
// 96 MMAs per 16 ldsm per s-step (6 MMA/ldsm), ~180 regs, no spill @255 cap.
// EPI: 0 bias+split, 1 bias+f32, 2 mask+f32, 3 split, 4 add+f32
// ---------------------------------------------------------------------------
template <int EPI>
__global__ void __launch_bounds__(256, 1) gemm_mma(
    const __nv_bfloat16* __restrict__ Ah, const __nv_bfloat16* __restrict__ Al,
    const __nv_bfloat16* __restrict__ Bh, const __nv_bfloat16* __restrict__ Bl,
    int K, int Nt,
    long sA, long sB, long sC,
    const float* __restrict__ bias,
    const int* __restrict__ mask,
    const float* __restrict__ add,
    float* __restrict__ Cf,
    __nv_bfloat16* __restrict__ Ch, __nv_bfloat16* __restrict__ Cl)
{
    extern __shared__ __align__(16) char dsm[];
    constexpr uint32_t ROWB = 80;                       // 32 bf16 + 16B pad
    constexpr uint32_t OAH = 0;                         // 128*80 = 10240
    constexpr uint32_t OAL = 10240;
    constexpr uint32_t OBH = 20480;                     // 256*80 = 20480
    constexpr uint32_t OBL = 40960;
    constexpr uint32_t STAGE = 61440;                   // x3 = 184320

    const uint32_t smb = smem_u32(dsm);
    const int tid = threadIdx.x;
    const int lane = tid & 31;
    const int wid = tid >> 5;

    const int bm = blockIdx.y * 128;
    const int bn = blockIdx.x * 256;
    const long z = blockIdx.z;

    const __nv_bfloat16* bAh = Ah + z * sA;
    const __nv_bfloat16* bAl = Al + z * sA;
    const __nv_bfloat16* bBh = Bh + z * sB;
    const __nv_bfloat16* bBl = Bl + z * sB;

    // loader: A tile = 512 16B-chunks (2/thread), B tile = 1024 (4/thread)
    const int a0 = tid * 2,     aR0 = a0 >> 2,       aS0 = a0 & 3;
    const int a1 = tid * 2 + 1, aR1 = a1 >> 2,       aS1 = a1 & 3;

#define LOAD_STAGE(stg, k0) do {                                                           \
    uint32_t sb_ = smb + (uint32_t)(stg) * STAGE;                                          \
    CP16(sb_ + OAH + aR0 * ROWB + aS0 * 16, bAh + (size_t)(bm + aR0) * K + (k0) + aS0 * 8);\
    CP16(sb_ + OAH + aR1 * ROWB + aS1 * 16, bAh + (size_t)(bm + aR1) * K + (k0) + aS1 * 8);\
    CP16(sb_ + OAL + aR0 * ROWB + aS0 * 16, bAl + (size_t)(bm + aR0) * K + (k0) + aS0 * 8);\
    CP16(sb_ + OAL + aR1 * ROWB + aS1 * 16, bAl + (size_t)(bm + aR1) * K + (k0) + aS1 * 8);\
    _Pragma("unroll")                                                                      \
    for (int i_ = 0; i_ < 4; i_++) {                                                       \
        int id_ = tid * 4 + i_, rB_ = id_ >> 2, sB_ = id_ & 3;                             \
        CP16(sb_ + OBH + rB_ * ROWB + sB_ * 16, bBh + (size_t)(bn + rB_) * K + (k0) + sB_ * 8);\
        CP16(sb_ + OBL + rB_ * ROWB + sB_ * 16, bBl + (size_t)(bn + rB_) * K + (k0) + sB_ * 8);\
    }                                                                                      \
} while (0)

    float acc[4][8][4];
#pragma unroll
    for (int i = 0; i < 4; i++)
#pragma unroll
        for (int j = 0; j < 8; j++)
#pragma unroll
            for (int t = 0; t < 4; t++) acc[i][j][t] = 0.0f;

    const int nk = K >> 5;
    LOAD_STAGE(0, 0);
    CP_COMMIT();
    LOAD_STAGE(1, 32);
    CP_COMMIT();

    const int m0w = (wid & 1) * 64;      // 2 warps in M
    const int n0w = (wid >> 1) * 64;     // 4 warps in N
    const int lrow = lane & 15;
    const uint32_t lcb = (uint32_t)(lane >> 4) * 16;

    for (int c = 0; c < nk; c++) {
        CP_WAIT1();
        __syncthreads();
        if (c + 2 < nk) { LOAD_STAGE((c + 2) % 3, (c + 2) * 32); }
        CP_COMMIT();

        const uint32_t sb = smb + (uint32_t)(c % 3) * STAGE;
#pragma unroll
        for (int s = 0; s < 2; s++) {
            const uint32_t kb = (uint32_t)s * 32 + lcb;

            // B fragments resident: 32 regs (8 ni x 2 k-halves, hi + lo)
            uint32_t bh[8][2], bl[8][2];
#pragma unroll
            for (int nj = 0; nj < 4; nj++) {
                uint32_t t0, t1, t2, t3;
                ldsm4(t0, t1, t2, t3,
                      sb + OBH + (uint32_t)(n0w + 16 * nj + lrow) * ROWB + kb);
                bh[2*nj][0] = t0; bh[2*nj][1] = t2;
                bh[2*nj+1][0] = t1; bh[2*nj+1][1] = t3;
                ldsm4(t0, t1, t2, t3,
                      sb + OBL + (uint32_t)(n0w + 16 * nj + lrow) * ROWB + kb);
                bl[2*nj][0] = t0; bl[2*nj][1] = t2;
                bl[2*nj+1][0] = t1; bl[2*nj+1][1] = t3;
            }

            // A streamed per-mi: 8 transient regs; 24 MMAs per 2 ldsm
#pragma unroll
            for (int mi = 0; mi < 4; mi++) {
                uint32_t ah[4], al[4];
                ldsm4(ah[0], ah[1], ah[2], ah[3],
                      sb + OAH + (uint32_t)(m0w + 16 * mi + lrow) * ROWB + kb);
                ldsm4(al[0], al[1], al[2], al[3],
                      sb + OAL + (uint32_t)(m0w + 16 * mi + lrow) * ROWB + kb);
#pragma unroll
                for (int ni = 0; ni < 8; ni++) mma16816(acc[mi][ni], ah, bh[ni]);
#pragma unroll
                for (int ni = 0; ni < 8; ni++) mma16816(acc[mi][ni], ah, bl[ni]);
#pragma unroll
                for (int ni = 0; ni < 8; ni++) mma16816(acc[mi][ni], al, bh[ni]);
            }
        }
    }

    // ---------------- epilogue ----------------
    const int* maskz = (EPI == 2) ? (mask + z * sC) : nullptr;
    float* Cfz = Cf ? Cf + z * sC : nullptr;
    __nv_bfloat16* Chz = Ch ? Ch + z * sC : nullptr;
    __nv_bfloat16* Clz = Cl ? Cl + z * sC : nullptr;

#pragma unroll
    for (int mi = 0; mi < 4; mi++) {
#pragma unroll
        for (int ni = 0; ni < 8; ni++) {
            float* a = acc[mi][ni];
            const int r = bm + m0w + 16 * mi + (lane >> 2);
            const int cc = bn + n0w + 8 * ni + (lane & 3) * 2;
            float v0 = a[0], v1 = a[1], v2 = a[2], v3 = a[3];

            if (EPI == 0 || EPI == 1) {
                float2 b = *(const float2*)&bias[cc];
                v0 += b.x; v1 += b.y; v2 += b.x; v3 += b.y;
            }
            if (EPI == 2) {
                int2 mA = *(const int2*)&maskz[(size_t)r * Nt + cc];
                int2 mB = *(const int2*)&maskz[(size_t)(r + 8) * Nt + cc];
                if (mA.x) v0 = -1e18f;
                if (mA.y) v1 = -1e18f;
                if (mB.x) v2 = -1e18f;
                if (mB.y) v3 = -1e18f;
            }
            if (EPI == 4) {
                float2 aA = *(const float2*)&add[(size_t)r * Nt + cc];
                float2 aB = *(const float2*)&add[(size_t)(r + 8) * Nt + cc];
                v0 += aA.x; v1 += aA.y; v2 += aB.x; v3 += aB.y;
            }

            if (EPI == 0 || EPI == 3) {
                *(uint32_t*)&Chz[(size_t)r * Nt + cc]       = pack_hi2(v0, v1);
                *(uint32_t*)&Clz[(size_t)r * Nt + cc]       = pack_lo2(v0, v1);
                *(uint32_t*)&Chz[(size_t)(r + 8) * Nt + cc] = pack_hi2(v2, v3);
                *(uint32_t*)&Clz[(size_t)(r + 8) * Nt + cc] = pack_lo2(v2, v3);
            } else {
                *(float2*)&Cfz[(size_t)r * Nt + cc]       = make_float2(v0, v1);
                *(float2*)&Cfz[(size_t)(r + 8) * Nt + cc] = make_float2(v2, v3);
            }
        }
    }
}

// ---------------------------------------------------------------------------
// fp32 -> bf16 hi/lo split (elementwise, vectorized)
// ---------------------------------------------------------------------------
__global__ void convsplit_kernel(const float* __restrict__ x,
                                 __nv_bfloat16* __restrict__ h,
                                 __nv_bfloat16* __restrict__ l, int n)
{
    int i = (blockIdx.x * 256 + threadIdx.x) * 4;
    if (i < n) {
        float4 v = *(const float4*)&x[i];
        *(uint32_t*)&h[i]     = pack_hi2(v.x, v.y);
        *(uint32_t*)&h[i + 2] = pack_hi2(v.z, v.w);
        *(uint32_t*)&l[i]     = pack_lo2(v.x, v.y);
        *(uint32_t*)&l[i + 2] = pack_lo2(v.z, v.w);
    }
}

// 4 weight matrices in one launch (z selects)
__global__ void convsplit4_kernel(
    const float* __restrict__ w0, const float* __restrict__ w1,
    const float* __restrict__ w2, const float* __restrict__ w3,
    __nv_bfloat16* __restrict__ h0, __nv_bfloat16* __restrict__ l0,
    __nv_bfloat16* __restrict__ h1, __nv_bfloat16* __restrict__ l1,
    __nv_bfloat16* __restrict__ h2, __nv_bfloat16* __restrict__ l2,
    __nv_bfloat16* __restrict__ h3, __nv_bfloat16* __restrict__ l3)
{
    const int zz = blockIdx.z;
    const float* x = (zz == 0) ? w0 : (zz == 1) ? w1 : (zz == 2) ? w2 : w3;
    __nv_bfloat16* h = (zz == 0) ? h0 : (zz == 1) ? h1 : (zz == 2) ? h2 : h3;
    __nv_bfloat16* l = (zz == 0) ? l0 : (zz == 1) ? l1 : (zz == 2) ? l2 : l3;
    int i = (blockIdx.x * 256 + threadIdx.x) * 4;
    float4 v = *(const float4*)&x[i];
    *(uint32_t*)&h[i]     = pack_hi2(v.x, v.y);
    *(uint32_t*)&h[i + 2] = pack_hi2(v.z, v.w);
    *(uint32_t*)&l[i]     = pack_lo2(v.x, v.y);
    *(uint32_t*)&l[i + 2] = pack_lo2(v.z, v.w);
}

// ---------------------------------------------------------------------------
// v[T,E] fp32 (batched) -> vT hi/lo [E,T] bf16
// ---------------------------------------------------------------------------
__global__ void transconv_kernel(const float* __restrict__ v,
                                 __nv_bfloat16* __restrict__ th,
                                 __nv_bfloat16* __restrict__ tl)
{
    __shared__ float tile[32][33];
    const long z = blockIdx.z;
    const float* vz = v + z * ((size_t)T_ * E_);
    __nv_bfloat16* thz = th + z * ((size_t)T_ * E_);
    __nv_bfloat16* tlz = tl + z * ((size_t)T_ * E_);
    const int t0 = blockIdx.x * 32;
    const int e0 = blockIdx.y * 32;
    const int tx = threadIdx.x, ty = threadIdx.y;
#pragma unroll
    for (int i = 0; i < 32; i += 8)
        tile[ty + i][tx] = vz[(size_t)(t0 + ty + i) * E_ + e0 + tx];
    __syncthreads();
#pragma unroll
    for (int i = 0; i < 32; i += 8) {
        float x = tile[tx][ty + i];
        __nv_bfloat16 hi = __float2bfloat16(x);
        size_t o = (size_t)(e0 + ty + i) * T_ + t0 + tx;
        thz[o] = hi;
        tlz[o] = __float2bfloat16(x - __bfloat162float(hi));
    }
}

// ---------------------------------------------------------------------------
// reductions
// ---------------------------------------------------------------------------
__device__ __forceinline__ float block_sum_256(float v) {
    __shared__ float sh[8];
    __shared__ float res;
#pragma unroll
    for (int o = 16; o > 0; o >>= 1) v += __shfl_xor_sync(0xffffffffu, v, o);
    const int w = threadIdx.x >> 5;
    if ((threadIdx.x & 31) == 0) sh[w] = v;
    __syncthreads();
    if (threadIdx.x == 0) {
        float t = 0.0f;
#pragma unroll
        for (int i = 0; i < 8; i++) t += sh[i];
        res = t;
    }
    __syncthreads();
    return res;
}
__device__ __forceinline__ float block_max_256(float v) {
    __shared__ float shm[8];
    __shared__ float resm;
#pragma unroll
    for (int o = 16; o > 0; o >>= 1) v = fmaxf(v, __shfl_xor_sync(0xffffffffu, v, o));
    const int w = threadIdx.x >> 5;
    if ((threadIdx.x & 31) == 0) shm[w] = v;
    __syncthreads();
    if (threadIdx.x == 0) {
        float t = shm[0];
#pragma unroll
        for (int i = 1; i < 8; i++) t = fmaxf(t, shm[i]);
        resm = t;
    }
    __syncthreads();
    return resm;
}

// ---------------------------------------------------------------------------
// softmax over T, emits bf16 hi/lo weights
// ---------------------------------------------------------------------------
__global__ void __launch_bounds__(256) softmax_split_kernel(
    const float* __restrict__ lg,
    __nv_bfloat16* __restrict__ ph, __nv_bfloat16* __restrict__ pl)
{
    const size_t base = (size_t)blockIdx.x * T_;
    const float* p = lg + base;
    const int t = threadIdx.x;
    float vals[8];
    float mx = -__int_as_float(0x7f800000);
#pragma unroll
    for (int i = 0; i < 8; i++) {
        vals[i] = p[t + i * 256];
        mx = fmaxf(mx, vals[i]);
    }
    mx = block_max_256(mx);
    float s = 0.0f;
#pragma unroll
    for (int i = 0; i < 8; i++) {
        vals[i] = __expf(vals[i] - mx);
        s += vals[i];
    }
    s = block_sum_256(s);
    const float inv = 1.0f / s;
#pragma unroll
    for (int i = 0; i < 8; i++) {
        float w = vals[i] * inv;
        __nv_bfloat16 hi = __float2bfloat16(w);
        ph[base + t + i * 256] = hi;
        pl[base + t + i * 256] = __float2bfloat16(w - __bfloat162float(hi));
    }
}

// ---------------------------------------------------------------------------
// LayerNorm + residual
// ---------------------------------------------------------------------------
__global__ void __launch_bounds__(256) layernorm_kernel(
    const float* __restrict__ x, const float* __restrict__ enc,
    const float* __restrict__ gamma, const float* __restrict__ beta,
    float* __restrict__ out)
{
    const size_t row = blockIdx.x;
    const float* xr = x + row * E_;
    const float* er = enc + row * E_;
    float* orow = out + row * E_;
    const int t = threadIdx.x;

    const float x0 = xr[t];
    const float x1 = xr[t + 256];
    const float mean = block_sum_256(x0 + x1) * (1.0f / E_);
    const float d0 = x0 - mean;
    const float d1 = x1 - mean;
    const float var = block_sum_256(d0 * d0 + d1 * d1) * (1.0f / E_);
    const float inv = 1.0f / (sqrtf(var) + EPSF);

    orow[t]       = er[t]       + gamma[t]       * d0 * inv + beta[t];
    orow[t + 256] = er[t + 256] + gamma[t + 256] * d1 * inv + beta[t + 256];
}

// ---------------------------------------------------------------------------
// launch
// ---------------------------------------------------------------------------
extern "C" void kernel_launch(void* const* d_in, const int* in_sizes, int n_in,
                              void* d_out, int out_size)
{
    const float* enc  = (const float*)d_in[0];
    const float* emo  = (const float*)d_in[1];
    const int*   mask = (const int*)d_in[2];
    const float* Wq   = (const float*)d_in[3];
    const float* bq   = (const float*)d_in[4];
    const float* Wk   = (const float*)d_in[5];
    const float* bk   = (const float*)d_in[6];
    const float* Wv   = (const float*)d_in[7];
    const float* bv   = (const float*)d_in[8];
    const float* Wo   = (const float*)d_in[9];
    const float* gamma = (const float*)d_in[10];
    const float* beta  = (const float*)d_in[11];
    float* out = (float*)d_out;

    __nv_bfloat16 *encH,*encL,*emoH,*emoL,*WqH,*WqL,*WkH,*WkL,*WvH,*WvL,*WoH,*WoL;
    __nv_bfloat16 *qH,*qL,*kH,*kL,*vTH,*vTL,*pH,*pL,*ctxH,*ctxL;
    float *v, *lg, *tmp;
    cudaGetSymbolAddress((void**)&encH, g_encH); cudaGetSymbolAddress((void**)&encL, g_encL);
    cudaGetSymbolAddress((void**)&emoH, g_emoH); cudaGetSymbolAddress((void**)&emoL, g_emoL);
    cudaGetSymbolAddress((void**)&WqH, g_WqH); cudaGetSymbolAddress((void**)&WqL, g_WqL);
    cudaGetSymbolAddress((void**)&WkH, g_WkH); cudaGetSymbolAddress((void**)&WkL, g_WkL);
    cudaGetSymbolAddress((void**)&WvH, g_WvH); cudaGetSymbolAddress((void**)&WvL, g_WvL);
    cudaGetSymbolAddress((void**)&WoH, g_WoH); cudaGetSymbolAddress((void**)&WoL, g_WoL);
    cudaGetSymbolAddress((void**)&qH, g_qH); cudaGetSymbolAddress((void**)&qL, g_qL);
    cudaGetSymbolAddress((void**)&kH, g_kH); cudaGetSymbolAddress((void**)&kL, g_kL);
    cudaGetSymbolAddress((void**)&vTH, g_vTH); cudaGetSymbolAddress((void**)&vTL, g_vTL);
    cudaGetSymbolAddress((void**)&pH, g_pH); cudaGetSymbolAddress((void**)&pL, g_pL);
    cudaGetSymbolAddress((void**)&ctxH, g_ctxH); cudaGetSymbolAddress((void**)&ctxL, g_ctxL);
    cudaGetSymbolAddress((void**)&v, g_v);
    cudaGetSymbolAddress((void**)&lg, g_logits);
    cudaGetSymbolAddress((void**)&tmp, g_tmp);

    const int SMEM_SZ = 3 * 61440;   // 184320
    cudaFuncSetAttribute(gemm_mma<0>, cudaFuncAttributeMaxDynamicSharedMemorySize, SMEM_SZ);
    cudaFuncSetAttribute(gemm_mma<1>, cudaFuncAttributeMaxDynamicSharedMemorySize, SMEM_SZ);
    cudaFuncSetAttribute(gemm_mma<2>, cudaFuncAttributeMaxDynamicSharedMemorySize, SMEM_SZ);
    cudaFuncSetAttribute(gemm_mma<3>, cudaFuncAttributeMaxDynamicSharedMemorySize, SMEM_SZ);
    cudaFuncSetAttribute(gemm_mma<4>, cudaFuncAttributeMaxDynamicSharedMemorySize, SMEM_SZ);

    // 1-2) input splits
    convsplit_kernel<<<NSE / 1024, 256>>>(enc, encH, encL, NSE);
    convsplit_kernel<<<NSE / 1024, 256>>>(emo, emoH, emoL, NSE);
    // 3) all 4 weight splits in one launch
    convsplit4_kernel<<<dim3((E_*E_) / 1024, 1, 4), 256>>>(
        Wq, Wk, Wv, Wo, WqH, WqL, WkH, WkL, WvH, WvL, WoH, WoL);

    // 4-5) Q and K projections: [16384,512] x [512,512]^T
    const dim3 gp(E_ / 256, (B_ * S_) / 128, 1);
    gemm_mma<0><<<gp, 256, SMEM_SZ>>>(encH, encL, WqH, WqL, E_, E_, 0, 0, 0,
                                      bq, nullptr, nullptr, nullptr, qH, qL);
    gemm_mma<0><<<gp, 256, SMEM_SZ>>>(emoH, emoL, WkH, WkL, E_, E_, 0, 0, 0,
                                      bk, nullptr, nullptr, nullptr, kH, kL);

    // 6) logits = q k^T + mask   (profiled launch: -s 5 -c 1)
    const dim3 gl(T_ / 256, S_ / 128, B_);
    gemm_mma<2><<<gl, 256, SMEM_SZ>>>(qH, qL, kH, kL, E_, T_,
                                      (long)S_ * E_, (long)T_ * E_, (long)S_ * T_,
                                      nullptr, mask, nullptr, lg, nullptr, nullptr);

    // 7) V projection
    gemm_mma<1><<<gp, 256, SMEM_SZ>>>(emoH, emoL, WvH, WvL, E_, E_, 0, 0, 0,
                                      bv, nullptr, nullptr, v, nullptr, nullptr);

    // 8) v -> vT hi/lo
    transconv_kernel<<<dim3(T_ / 32, E_ / 32, B_), dim3(32, 8)>>>(v, vTH, vTL);

    // 9) softmax -> P hi/lo
    softmax_split_kernel<<<B_ * S_, 256>>>(lg, pH, pL);

    // 10) ctx = P @ v  (B = vT [E,T])
    const dim3 gc(E_ / 256, S_ / 128, B_);
    gemm_mma<3><<<gc, 256, SMEM_SZ>>>(pH, pL, vTH, vTL, T_, E_,
                                      (long)S_ * T_, (long)T_ * E_, (long)S_ * E_,
                                      nullptr, nullptr, nullptr, nullptr, ctxH, ctxL);

    // 11) tmp = ctx @ Wo^T + enc
    const dim3 go(E_ / 256, (B_ * S_) / 128, 1);
    gemm_mma<4><<<go, 256, SMEM_SZ>>>(ctxH, ctxL, WoH, WoL, E_, E_, 0, 0, 0,
                                      nullptr, nullptr, enc, tmp, nullptr, nullptr);

    // 12) out = enc + LN(tmp)
    layernorm_kernel<<<B_ * S_, 256>>>(tmp, enc, gamma, beta, out);
}

// round 12
// speedup vs baseline: 1.4718x; 1.4718x over previous
#include <cuda_runtime.h>
#include <cuda_fp16.h>
#include <cstdint>

#define EPSF 1e-6f

constexpr int B_ = 8;
constexpr int S_ = 2048;
constexpr int T_ = 2048;
constexpr int E_ = 512;

constexpr int NSE = B_ * S_ * E_;               // 8388608
constexpr size_t NST = (size_t)B_ * S_ * T_;    // 33554432

// ---------------- scratch (device globals) ----------------
__device__ __half g_encH[NSE], g_encL[NSE];
__device__ __half g_emoH[NSE], g_emoL[NSE];
__device__ __half g_WqH[E_*E_], g_WqL[E_*E_];
__device__ __half g_WkH[E_*E_], g_WkL[E_*E_];
__device__ __half g_WvH[E_*E_], g_WvL[E_*E_];
__device__ __half g_WoH[E_*E_], g_WoL[E_*E_];
__device__ __half g_qH[NSE], g_qL[NSE];
__device__ __half g_kH[NSE], g_kL[NSE];
__device__ float  g_v[NSE];
__device__ __half g_vTH[NSE], g_vTL[NSE];
__device__ float  g_logits[NST];
__device__ __half g_pH[NST];
__device__ __half g_ctxH[NSE];
__device__ float  g_tmp[NSE];

// ---------------- helpers ----------------
__device__ __forceinline__ uint32_t smem_u32(const void* p) {
    uint32_t a;
    asm("{ .reg .u64 t; cvta.to.shared.u64 t, %1; cvt.u32.u64 %0, t; }" : "=r"(a) : "l"(p));
    return a;
}
#define CP16(dst, src) asm volatile("cp.async.cg.shared.global [%0], [%1], 16;" :: "r"(dst), "l"(src))
#define CP_COMMIT()    asm volatile("cp.async.commit_group;")
#define CP_WAIT0()     asm volatile("cp.async.wait_group 0;")

__device__ __forceinline__ void ldsm4(uint32_t& r0, uint32_t& r1, uint32_t& r2, uint32_t& r3, uint32_t a) {
    asm volatile("ldmatrix.sync.aligned.m8n8.x4.shared.b16 {%0,%1,%2,%3}, [%4];"
                 : "=r"(r0), "=r"(r1), "=r"(r2), "=r"(r3) : "r"(a));
}
__device__ __forceinline__ void mma16816(float* c, const uint32_t* a, const uint32_t* b) {
    asm volatile("mma.sync.aligned.m16n8k16.row.col.f32.f16.f16.f32 "
                 "{%0,%1,%2,%3}, {%4,%5,%6,%7}, {%8,%9}, {%0,%1,%2,%3};"
                 : "+f"(c[0]), "+f"(c[1]), "+f"(c[2]), "+f"(c[3])
                 : "r"(a[0]), "r"(a[1]), "r"(a[2]), "r"(a[3]), "r"(b[0]), "r"(b[1]));
}
__device__ __forceinline__ uint32_t pack_hi2(float x, float y) {
    unsigned short hx = __half_as_ushort(__float2half_rn(x));
    unsigned short hy = __half_as_ushort(__float2half_rn(y));
    return (uint32_t)hx | ((uint32_t)hy << 16);
}
__device__ __forceinline__ uint32_t pack_lo2(float x, float y) {
    float hx = __half2float(__float2half_rn(x));
    float hy = __half2float(__float2half_rn(y));
    unsigned short lx = __half_as_ushort(__float2half_rn(x - hx));
    unsigned short ly = __half_as_ushort(__float2half_rn(y - hy));
    return (uint32_t)lx | ((uint32_t)ly << 16);
}

// ---------------------------------------------------------------------------
// fp16-split GEMM via mma.sync, NT form: C[m,n] = sum_k A[m,k]*B[n,k].
// Block tile 128x256, BK=64, 512 threads (16 warps, warp tile 64x32),
// 2-stage cp.async. NPROD=3: AhBh+AhBl+AlBh (near-fp32).
// NPROD=2: AhBh+AhBl (A-lo never loaded; err ~2^-12, used on diluted paths).
// EPI: 0 bias+split(hi,lo), 1 bias+f32, 2 mask+f32, 4 add+f32, 5 split hi-only
// ---------------------------------------------------------------------------
template <int EPI, int NPROD>
__global__ void __launch_bounds__(512, 1) gemm_mma(
    const __half* __restrict__ Ah, const __half* __restrict__ Al,
    const __half* __restrict__ Bh, const __half* __restrict__ Bl,
    int K, int Nt,
    long sA, long sB, long sC,
    const float* __restrict__ bias,
    const int* __restrict__ mask,
    const float* __restrict__ add,
    float* __restrict__ Cf,
    __half* __restrict__ Ch, __half* __restrict__ Cl)
{
    extern __shared__ __align__(16) char dsm[];
    constexpr uint32_t ROWB = 144;                      // 64 fp16 (128B) + 16B pad
    constexpr uint32_t OAH = 0;                         // A-hi: 128*144 = 18432
    constexpr uint32_t OAL = 18432;                     // A-lo (NPROD=3 only)
    constexpr uint32_t OBH = (NPROD == 3) ? 36864u : 18432u;
    constexpr uint32_t OBL = OBH + 36864;               // B tiles: 256*144
    constexpr uint32_t STAGE = OBL + 36864;             // 110592 or 92160

    const uint32_t smb = smem_u32(dsm);
    const int tid = threadIdx.x;
    const int lane = tid & 31;
    const int wid = tid >> 5;

    const int bm = blockIdx.y * 128;
    const int bn = blockIdx.x * 256;
    const long z = blockIdx.z;

    const __half* bAh = Ah + z * sA;
    const __half* bAl = (NPROD == 3) ? (Al + z * sA) : nullptr;
    const __half* bBh = Bh + z * sB;
    const __half* bBl = Bl + z * sB;

    // loader: per stage A = 1024 16B-chunks per tensor (2/thr), B = 2048 (4/thr)
#define LOAD_STAGE(stg, k0) do {                                                             \
    uint32_t sb_ = smb + (uint32_t)(stg) * STAGE;                                            \
    _Pragma("unroll")                                                                        \
    for (int i_ = 0; i_ < 2; i_++) {                                                         \
        int id_ = tid + i_ * 512, rA_ = id_ >> 3, sA_ = id_ & 7;                             \
        CP16(sb_ + OAH + rA_ * ROWB + sA_ * 16, bAh + (size_t)(bm + rA_) * K + (k0) + sA_ * 8);\
        if (NPROD == 3)                                                                      \
            CP16(sb_ + OAL + rA_ * ROWB + sA_ * 16, bAl + (size_t)(bm + rA_) * K + (k0) + sA_ * 8);\
    }                                                                                        \
    _Pragma("unroll")                                                                        \
    for (int i_ = 0; i_ < 4; i_++) {                                                         \
        int id_ = tid + i_ * 512, rB_ = id_ >> 3, sB_ = id_ & 7;                             \
        CP16(sb_ + OBH + rB_ * ROWB + sB_ * 16, bBh + (size_t)(bn + rB_) * K + (k0) + sB_ * 8);\
        CP16(sb_ + OBL + rB_ * ROWB + sB_ * 16, bBl + (size_t)(bn + rB_) * K + (k0) + sB_ * 8);\
    }                                                                                        \
} while (0)

    float acc[4][4][4];
#pragma unroll
    for (int i = 0; i < 4; i++)
#pragma unroll
        for (int j = 0; j < 4; j++)
#pragma unroll
            for (int t = 0; t < 4; t++) acc[i][j][t] = 0.0f;

    const int nk = K >> 6;
    LOAD_STAGE(0, 0);
    CP_COMMIT();

    const int m0w = (wid & 1) * 64;      // 2 warps in M
    const int n0w = (wid >> 1) * 32;     // 8 warps in N
    const int lrow = lane & 15;
    const uint32_t lcb = (uint32_t)(lane >> 4) * 16;

    for (int c = 0; c < nk; c++) {
        CP_WAIT0();
        __syncthreads();
        if (c + 1 < nk) { LOAD_STAGE((c + 1) & 1, (c + 1) * 64); CP_COMMIT(); }

        const uint32_t sb = smb + (uint32_t)(c & 1) * STAGE;
#pragma unroll
        for (int s = 0; s < 4; s++) {
            const uint32_t kb = (uint32_t)s * 32 + lcb;

            if (NPROD == 3) {
                uint32_t ah[4][4], al[4][4];
#pragma unroll
                for (int mi = 0; mi < 4; mi++) {
                    ldsm4(ah[mi][0], ah[mi][1], ah[mi][2], ah[mi][3],
                          sb + OAH + (uint32_t)(m0w + 16 * mi + lrow) * ROWB + kb);
                    ldsm4(al[mi][0], al[mi][1], al[mi][2], al[mi][3],
                          sb + OAL + (uint32_t)(m0w + 16 * mi + lrow) * ROWB + kb);
                }
#pragma unroll
                for (int nj = 0; nj < 2; nj++) {
                    uint32_t t0, t1, t2, t3;
                    uint32_t b0[2], b1[2];
                    ldsm4(t0, t1, t2, t3,
                          sb + OBH + (uint32_t)(n0w + 16 * nj + lrow) * ROWB + kb);
                    b0[0] = t0; b0[1] = t2; b1[0] = t1; b1[1] = t3;
#pragma unroll
                    for (int mi = 0; mi < 4; mi++) mma16816(acc[mi][2*nj],   ah[mi], b0);
#pragma unroll
                    for (int mi = 0; mi < 4; mi++) mma16816(acc[mi][2*nj+1], ah[mi], b1);
#pragma unroll
                    for (int mi = 0; mi < 4; mi++) mma16816(acc[mi][2*nj],   al[mi], b0);
#pragma unroll
                    for (int mi = 0; mi < 4; mi++) mma16816(acc[mi][2*nj+1], al[mi], b1);
                    ldsm4(t0, t1, t2, t3,
                          sb + OBL + (uint32_t)(n0w + 16 * nj + lrow) * ROWB + kb);
                    b0[0] = t0; b0[1] = t2; b1[0] = t1; b1[1] = t3;
#pragma unroll
                    for (int mi = 0; mi < 4; mi++) mma16816(acc[mi][2*nj],   ah[mi], b0);
#pragma unroll
                    for (int mi = 0; mi < 4; mi++) mma16816(acc[mi][2*nj+1], ah[mi], b1);
                }
            } else {
                uint32_t ah[4][4];
#pragma unroll
                for (int mi = 0; mi < 4; mi++)
                    ldsm4(ah[mi][0], ah[mi][1], ah[mi][2], ah[mi][3],
                          sb + OAH + (uint32_t)(m0w + 16 * mi + lrow) * ROWB + kb);
#pragma unroll
                for (int nj = 0; nj < 2; nj++) {
                    uint32_t t0, t1, t2, t3;
                    uint32_t b0[2], b1[2];
                    ldsm4(t0, t1, t2, t3,
                          sb + OBH + (uint32_t)(n0w + 16 * nj + lrow) * ROWB + kb);
                    b0[0] = t0; b0[1] = t2; b1[0] = t1; b1[1] = t3;
#pragma unroll
                    for (int mi = 0; mi < 4; mi++) mma16816(acc[mi][2*nj],   ah[mi], b0);
#pragma unroll
                    for (int mi = 0; mi < 4; mi++) mma16816(acc[mi][2*nj+1], ah[mi], b1);
                    ldsm4(t0, t1, t2, t3,
                          sb + OBL + (uint32_t)(n0w + 16 * nj + lrow) * ROWB + kb);
                    b0[0] = t0; b0[1] = t2; b1[0] = t1; b1[1] = t3;
#pragma unroll
                    for (int mi = 0; mi < 4; mi++) mma16816(acc[mi][2*nj],   ah[mi], b0);
#pragma unroll
                    for (int mi = 0; mi < 4; mi++) mma16816(acc[mi][2*nj+1], ah[mi], b1);
                }
            }
        }
    }

    // ---------------- epilogue ----------------
    const int* maskz = (EPI == 2) ? (mask + z * sC) : nullptr;
    float* Cfz = Cf ? Cf + z * sC : nullptr;
    __half* Chz = Ch ? Ch + z * sC : nullptr;
    __half* Clz = Cl ? Cl + z * sC : nullptr;

#pragma unroll
    for (int mi = 0; mi < 4; mi++) {
#pragma unroll
        for (int ni = 0; ni < 4; ni++) {
            float* a = acc[mi][ni];
            const int r = bm + m0w + 16 * mi + (lane >> 2);
            const int cc = bn + n0w + 8 * ni + (lane & 3) * 2;
            float v0 = a[0], v1 = a[1], v2 = a[2], v3 = a[3];

            if (EPI == 0 || EPI == 1) {
                float2 b = *(const float2*)&bias[cc];
                v0 += b.x; v1 += b.y; v2 += b.x; v3 += b.y;
            }
            if (EPI == 2) {
                int2 mA = *(const int2*)&maskz[(size_t)r * Nt + cc];
                int2 mB = *(const int2*)&maskz[(size_t)(r + 8) * Nt + cc];
                if (mA.x) v0 = -1e18f;
                if (mA.y) v1 = -1e18f;
                if (mB.x) v2 = -1e18f;
                if (mB.y) v3 = -1e18f;
            }
            if (EPI == 4) {
                float2 aA = *(const float2*)&add[(size_t)r * Nt + cc];
                float2 aB = *(const float2*)&add[(size_t)(r + 8) * Nt + cc];
                v0 += aA.x; v1 += aA.y; v2 += aB.x; v3 += aB.y;
            }

            if (EPI == 0) {
                *(uint32_t*)&Chz[(size_t)r * Nt + cc]       = pack_hi2(v0, v1);
                *(uint32_t*)&Clz[(size_t)r * Nt + cc]       = pack_lo2(v0, v1);
                *(uint32_t*)&Chz[(size_t)(r + 8) * Nt + cc] = pack_hi2(v2, v3);
                *(uint32_t*)&Clz[(size_t)(r + 8) * Nt + cc] = pack_lo2(v2, v3);
            } else if (EPI == 5) {
                *(uint32_t*)&Chz[(size_t)r * Nt + cc]       = pack_hi2(v0, v1);
                *(uint32_t*)&Chz[(size_t)(r + 8) * Nt + cc] = pack_hi2(v2, v3);
            } else {
                *(float2*)&Cfz[(size_t)r * Nt + cc]       = make_float2(v0, v1);
                *(float2*)&Cfz[(size_t)(r + 8) * Nt + cc] = make_float2(v2, v3);
            }
        }
    }
}

// ---------------------------------------------------------------------------
// fp32 -> fp16 hi/lo split (elementwise, vectorized)
// ---------------------------------------------------------------------------
__global__ void convsplit_kernel(const float* __restrict__ x,
                                 __half* __restrict__ h,
                                 __half* __restrict__ l, int n)
{
    int i = (blockIdx.x * 256 + threadIdx.x) * 4;
    if (i < n) {
        float4 v = *(const float4*)&x[i];
        *(uint32_t*)&h[i]     = pack_hi2(v.x, v.y);
        *(uint32_t*)&h[i + 2] = pack_hi2(v.z, v.w);
        *(uint32_t*)&l[i]     = pack_lo2(v.x, v.y);
        *(uint32_t*)&l[i + 2] = pack_lo2(v.z, v.w);
    }
}

// 4 weight matrices in one launch (z selects)
__global__ void convsplit4_kernel(
    const float* __restrict__ w0, const float* __restrict__ w1,
    const float* __restrict__ w2, const float* __restrict__ w3,
    __half* __restrict__ h0, __half* __restrict__ l0,
    __half* __restrict__ h1, __half* __restrict__ l1,
    __half* __restrict__ h2, __half* __restrict__ l2,
    __half* __restrict__ h3, __half* __restrict__ l3)
{
    const int zz = blockIdx.z;
    const float* x = (zz == 0) ? w0 : (zz == 1) ? w1 : (zz == 2) ? w2 : w3;
    __half* h = (zz == 0) ? h0 : (zz == 1) ? h1 : (zz == 2) ? h2 : h3;
    __half* l = (zz == 0) ? l0 : (zz == 1) ? l1 : (zz == 2) ? l2 : l3;
    int i = (blockIdx.x * 256 + threadIdx.x) * 4;
    float4 v = *(const float4*)&x[i];
    *(uint32_t*)&h[i]     = pack_hi2(v.x, v.y);
    *(uint32_t*)&h[i + 2] = pack_hi2(v.z, v.w);
    *(uint32_t*)&l[i]     = pack_lo2(v.x, v.y);
    *(uint32_t*)&l[i + 2] = pack_lo2(v.z, v.w);
}

// ---------------------------------------------------------------------------
// v[T,E] fp32 (batched) -> vT hi/lo [E,T] fp16
// ---------------------------------------------------------------------------
__global__ void transconv_kernel(const float* __restrict__ v,
                                 __half* __restrict__ th,
                                 __half* __restrict__ tl)
{
    __shared__ float tile[32][33];
    const long z = blockIdx.z;
    const float* vz = v + z * ((size_t)T_ * E_);
    __half* thz = th + z * ((size_t)T_ * E_);
    __half* tlz = tl + z * ((size_t)T_ * E_);
    const int t0 = blockIdx.x * 32;
    const int e0 = blockIdx.y * 32;
    const int tx = threadIdx.x, ty = threadIdx.y;
#pragma unroll
    for (int i = 0; i < 32; i += 8)
        tile[ty + i][tx] = vz[(size_t)(t0 + ty + i) * E_ + e0 + tx];
    __syncthreads();
#pragma unroll
    for (int i = 0; i < 32; i += 8) {
        float x = tile[tx][ty + i];
        __half hi = __float2half_rn(x);
        size_t o = (size_t)(e0 + ty + i) * T_ + t0 + tx;
        thz[o] = hi;
        tlz[o] = __float2half_rn(x - __half2float(hi));
    }
}

// ---------------------------------------------------------------------------
// reductions
// ---------------------------------------------------------------------------
__device__ __forceinline__ float block_sum_256(float v) {
    __shared__ float sh[8];
    __shared__ float res;
#pragma unroll
    for (int o = 16; o > 0; o >>= 1) v += __shfl_xor_sync(0xffffffffu, v, o);
    const int w = threadIdx.x >> 5;
    if ((threadIdx.x & 31) == 0) sh[w] = v;
    __syncthreads();
    if (threadIdx.x == 0) {
        float t = 0.0f;
#pragma unroll
        for (int i = 0; i < 8; i++) t += sh[i];
        res = t;
    }
    __syncthreads();
    return res;
}
__device__ __forceinline__ float block_max_256(float v) {
    __shared__ float shm[8];
    __shared__ float resm;
#pragma unroll
    for (int o = 16; o > 0; o >>= 1) v = fmaxf(v, __shfl_xor_sync(0xffffffffu, v, o));
    const int w = threadIdx.x >> 5;
    if ((threadIdx.x & 31) == 0) shm[w] = v;
    __syncthreads();
    if (threadIdx.x == 0) {
        float t = shm[0];
#pragma unroll
        for (int i = 1; i < 8; i++) t = fmaxf(t, shm[i]);
        resm = t;
    }
    __syncthreads();
    return resm;
}

// ---------------------------------------------------------------------------
// softmax over T, emits fp16 weights (hi only; PV is 2-product)
// ---------------------------------------------------------------------------
__global__ void __launch_bounds__(256) softmax_split_kernel(
    const float* __restrict__ lg, __half* __restrict__ ph)
{
    const size_t base = (size_t)blockIdx.x * T_;
    const float* p = lg + base;
    const int t = threadIdx.x;
    float vals[8];
    float mx = -__int_as_float(0x7f800000);
#pragma unroll
    for (int i = 0; i < 8; i++) {
        vals[i] = p[t + i * 256];
        mx = fmaxf(mx, vals[i]);
    }
    mx = block_max_256(mx);
    float s = 0.0f;
#pragma unroll
    for (int i = 0; i < 8; i++) {
        vals[i] = __expf(vals[i] - mx);
        s += vals[i];
    }
    s = block_sum_256(s);
    const float inv = 1.0f / s;
#pragma unroll
    for (int i = 0; i < 8; i++)
        ph[base + t + i * 256] = __float2half_rn(vals[i] * inv);
}

// ---------------------------------------------------------------------------
// LayerNorm + residual
// ---------------------------------------------------------------------------
__global__ void __launch_bounds__(256) layernorm_kernel(
    const float* __restrict__ x, const float* __restrict__ enc,
    const float* __restrict__ gamma, const float* __restrict__ beta,
    float* __restrict__ out)
{
    const size_t row = blockIdx.x;
    const float* xr = x + row * E_;
    const float* er = enc + row * E_;
    float* orow = out + row * E_;
    const int t = threadIdx.x;

    const float x0 = xr[t];
    const float x1 = xr[t + 256];
    const float mean = block_sum_256(x0 + x1) * (1.0f / E_);
    const float d0 = x0 - mean;
    const float d1 = x1 - mean;
    const float var = block_sum_256(d0 * d0 + d1 * d1) * (1.0f / E_);
    const float inv = 1.0f / (sqrtf(var) + EPSF);

    orow[t]       = er[t]       + gamma[t]       * d0 * inv + beta[t];
    orow[t + 256] = er[t + 256] + gamma[t + 256] * d1 * inv + beta[t + 256];
}

// ---------------------------------------------------------------------------
// launch
// ---------------------------------------------------------------------------
extern "C" void kernel_launch(void* const* d_in, const int* in_sizes, int n_in,
                              void* d_out, int out_size)
{
    const float* enc  = (const float*)d_in[0];
    const float* emo  = (const float*)d_in[1];
    const int*   mask = (const int*)d_in[2];
    const float* Wq   = (const float*)d_in[3];
    const float* bq   = (const float*)d_in[4];
    const float* Wk   = (const float*)d_in[5];
    const float* bk   = (const float*)d_in[6];
    const float* Wv   = (const float*)d_in[7];
    const float* bv   = (const float*)d_in[8];
    const float* Wo   = (const float*)d_in[9];
    const float* gamma = (const float*)d_in[10];
    const float* beta  = (const float*)d_in[11];
    float* out = (float*)d_out;

    __half *encH,*encL,*emoH,*emoL,*WqH,*WqL,*WkH,*WkL,*WvH,*WvL,*WoH,*WoL;
    __half *qH,*qL,*kH,*kL,*vTH,*vTL,*pH,*ctxH;
    float *v, *lg, *tmp;
    cudaGetSymbolAddress((void**)&encH, g_encH); cudaGetSymbolAddress((void**)&encL, g_encL);
    cudaGetSymbolAddress((void**)&emoH, g_emoH); cudaGetSymbolAddress((void**)&emoL, g_emoL);
    cudaGetSymbolAddress((void**)&WqH, g_WqH); cudaGetSymbolAddress((void**)&WqL, g_WqL);
    cudaGetSymbolAddress((void**)&WkH, g_WkH); cudaGetSymbolAddress((void**)&WkL, g_WkL);
    cudaGetSymbolAddress((void**)&WvH, g_WvH); cudaGetSymbolAddress((void**)&WvL, g_WvL);
    cudaGetSymbolAddress((void**)&WoH, g_WoH); cudaGetSymbolAddress((void**)&WoL, g_WoL);
    cudaGetSymbolAddress((void**)&qH, g_qH); cudaGetSymbolAddress((void**)&qL, g_qL);
    cudaGetSymbolAddress((void**)&kH, g_kH); cudaGetSymbolAddress((void**)&kL, g_kL);
    cudaGetSymbolAddress((void**)&vTH, g_vTH); cudaGetSymbolAddress((void**)&vTL, g_vTL);
    cudaGetSymbolAddress((void**)&pH, g_pH);
    cudaGetSymbolAddress((void**)&ctxH, g_ctxH);
    cudaGetSymbolAddress((void**)&v, g_v);
    cudaGetSymbolAddress((void**)&lg, g_logits);
    cudaGetSymbolAddress((void**)&tmp, g_tmp);

    const int SMEM3 = 2 * 110592;   // 221184 (NPROD=3)
    const int SMEM2 = 2 * 92160;    // 184320 (NPROD=2)
    cudaFuncSetAttribute(gemm_mma<0,3>, cudaFuncAttributeMaxDynamicSharedMemorySize, SMEM3);
    cudaFuncSetAttribute(gemm_mma<2,3>, cudaFuncAttributeMaxDynamicSharedMemorySize, SMEM3);
    cudaFuncSetAttribute(gemm_mma<1,2>, cudaFuncAttributeMaxDynamicSharedMemorySize, SMEM2);
    cudaFuncSetAttribute(gemm_mma<5,2>, cudaFuncAttributeMaxDynamicSharedMemorySize, SMEM2);
    cudaFuncSetAttribute(gemm_mma<4,2>, cudaFuncAttributeMaxDynamicSharedMemorySize, SMEM2);

    // 1-2) input splits
    convsplit_kernel<<<NSE / 1024, 256>>>(enc, encH, encL, NSE);
    convsplit_kernel<<<NSE / 1024, 256>>>(emo, emoH, emoL, NSE);
    // 3) all 4 weight splits in one launch
    convsplit4_kernel<<<dim3((E_*E_) / 1024, 1, 4), 256>>>(
        Wq, Wk, Wv, Wo, WqH, WqL, WkH, WkL, WvH, WvL, WoH, WoL);

    // 4-5) Q and K projections (3-product: feed logits, error-critical)
    const dim3 gp(E_ / 256, (B_ * S_) / 128, 1);
    gemm_mma<0,3><<<gp, 512, SMEM3>>>(encH, encL, WqH, WqL, E_, E_, 0, 0, 0,
                                      bq, nullptr, nullptr, nullptr, qH, qL);
    gemm_mma<0,3><<<gp, 512, SMEM3>>>(emoH, emoL, WkH, WkL, E_, E_, 0, 0, 0,
                                      bk, nullptr, nullptr, nullptr, kH, kL);

    // 6) logits = q k^T + mask (3-product; profiled launch: -s 5 -c 1)
    const dim3 gl(T_ / 256, S_ / 128, B_);
    gemm_mma<2,3><<<gl, 512, SMEM3>>>(qH, qL, kH, kL, E_, T_,
                                      (long)S_ * E_, (long)T_ * E_, (long)S_ * T_,
                                      nullptr, mask, nullptr, lg, nullptr, nullptr);

    // 7) V projection (2-product: diluted path)
    gemm_mma<1,2><<<gp, 512, SMEM2>>>(emoH, nullptr, WvH, WvL, E_, E_, 0, 0, 0,
                                      bv, nullptr, nullptr, v, nullptr, nullptr);

    // 8) v -> vT hi/lo
    transconv_kernel<<<dim3(T_ / 32, E_ / 32, B_), dim3(32, 8)>>>(v, vTH, vTL);

    // 9) softmax -> P hi (fp16)
    softmax_split_kernel<<<B_ * S_, 256>>>(lg, pH);

    // 10) ctx = P @ v (2-product; A = P hi only), ctx stored hi only
    const dim3 gc(E_ / 256, S_ / 128, B_);
    gemm_mma<5,2><<<gc, 512, SMEM2>>>(pH, nullptr, vTH, vTL, T_, E_,
                                      (long)S_ * T_, (long)T_ * E_, (long)S_ * E_,
                                      nullptr, nullptr, nullptr, nullptr, ctxH, nullptr);

    // 11) tmp = ctx @ Wo^T + enc (2-product)
    const dim3 go(E_ / 256, (B_ * S_) / 128, 1);
    gemm_mma<4,2><<<go, 512, SMEM2>>>(ctxH, nullptr, WoH, WoL, E_, E_, 0, 0, 0,
                                      nullptr, nullptr, enc, tmp, nullptr, nullptr);

    // 12) out = enc + LN(tmp)
    layernorm_kernel<<<B_ * S_, 256>>>(tmp, enc, gamma, beta, out);
}